// round 11
// baseline (speedup 1.0000x reference)
#include <cuda_runtime.h>
#include <cuda_fp16.h>
#include <math.h>

#define N_NODES   65536
#define E_EDGES   2097152
#define FEAT_IN   16
#define HID       32
#define N_GRAPHS  16
#define K_FC      131072      // 4096 * 32
#define FC_HID    256
#define LATENT    64
#define TILE_K    256
#define SLOTS     96          // bucket capacity per node; P(Poisson(32) > 96) ~ 1e-18

// Packed fp32x2 FMA (sm_103a FFMA2) — only reachable via PTX fma.rn.f32x2.
#define FMA_F32X2(d, a, b, c) \
    asm("fma.rn.f32x2 %0, %1, %2, %3;" : "=l"(d) : "l"(a), "l"(b), "l"(c))

// -------- scratch (static device globals; no runtime allocation) --------
__device__ float2 g_es[N_NODES * SLOTS];   // bucketed (src_bits, w); 48MB
__device__ int    g_cnt[N_NODES];          // zero-init; reset by fc1 each call
__device__ __half g_q[N_NODES * HID];      // projected features (gather source)
__device__ __half g_a[N_NODES * HID];      // post-conv activations (fp16)
__device__ float  g_h3[N_NODES * HID];     // layer-3 output (fp32, for FC1)
__device__ float  g_fc1[N_GRAPHS * FC_HID]; // zeroed by fill_kernel each call

__device__ __forceinline__ float elu(float v) {
    return v > 0.0f ? v : expm1f(v);
}

// Per-block dtype self-detection: if buffer is int64, hi-words of the first 32
// entries are all zero (indices < 65536); for int32 data they're random indices.
__device__ __forceinline__ int block_detect_is64(const unsigned int* ei32, int* s_is64) {
    if (threadIdx.x < 32) {
        unsigned int hi = ei32[threadIdx.x * 2 + 1];
        unsigned int ball = __ballot_sync(0xffffffffu, hi != 0u);
        if (threadIdx.x == 0) *s_is64 = (ball == 0u) ? 1 : 0;
    }
    __syncthreads();
    return *s_is64;
}

// -------- single-pass bucket fill + g_fc1 reset --------
__global__ __launch_bounds__(256)
void fill_kernel(const unsigned int* __restrict__ ei32, const float* __restrict__ w) {
    __shared__ int s_is64;
    int is64 = block_detect_is64(ei32, &s_is64);
    if (blockIdx.x == 0) {
        for (int i = threadIdx.x; i < N_GRAPHS * FC_HID; i += 256) g_fc1[i] = 0.0f;
    }
    long long e0 = (long long)blockIdx.x * 512 + threadIdx.x;
    int s0 = is64 ? (int)ei32[2 * e0]       : (int)ei32[e0];
    int s1 = is64 ? (int)ei32[2 * (e0+256)] : (int)ei32[e0 + 256];
    int d0 = is64 ? (int)ei32[2 * (E_EDGES + e0)]       : (int)ei32[E_EDGES + e0];
    int d1 = is64 ? (int)ei32[2 * (E_EDGES + e0 + 256)] : (int)ei32[E_EDGES + e0 + 256];
    float w0 = w[e0], w1 = w[e0 + 256];
    int p0 = atomicAdd(&g_cnt[d0], 1);
    int p1 = atomicAdd(&g_cnt[d1], 1);
    if (p0 < SLOTS) g_es[d0 * SLOTS + p0] = make_float2(__int_as_float(s0), w0);
    if (p1 < SLOTS) g_es[d1 * SLOTS + p1] = make_float2(__int_as_float(s1), w1);
}

// -------- proj0: q = x[N,16] @ W1[16,32]  (fp32 in, fp16 out) --------
// 256 threads; thread owns (node = tid>>2, 8 output cols j0..j0+7). 64 nodes/block.
__global__ __launch_bounds__(256)
void proj0_kernel(const float* __restrict__ x, const float* __restrict__ W,
                  __half* __restrict__ q) {
    __shared__ float Ws[FEAT_IN * HID];
    int tid = threadIdx.x;
    for (int i = tid; i < FEAT_IN * HID; i += 256) Ws[i] = W[i];
    __syncthreads();

    int n = blockIdx.x * 64 + (tid >> 2);
    int j0 = (tid & 3) * 8;
    const float4* xr = (const float4*)(x + n * FEAT_IN);
    float4 a0 = __ldg(&xr[0]), a1 = __ldg(&xr[1]);
    float4 a2 = __ldg(&xr[2]), a3 = __ldg(&xr[3]);
    float av[16] = {a0.x, a0.y, a0.z, a0.w, a1.x, a1.y, a1.z, a1.w,
                    a2.x, a2.y, a2.z, a2.w, a3.x, a3.y, a3.z, a3.w};
    float acc[8] = {0.f, 0.f, 0.f, 0.f, 0.f, 0.f, 0.f, 0.f};
#pragma unroll
    for (int k = 0; k < FEAT_IN; k++) {
        float ak = av[k];
#pragma unroll
        for (int j = 0; j < 8; j++)
            acc[j] = fmaf(ak, Ws[k * HID + j0 + j], acc[j]);
    }
    __half2 h01 = __float22half2_rn(make_float2(acc[0], acc[1]));
    __half2 h23 = __float22half2_rn(make_float2(acc[2], acc[3]));
    __half2 h45 = __float22half2_rn(make_float2(acc[4], acc[5]));
    __half2 h67 = __float22half2_rn(make_float2(acc[6], acc[7]));
    uint4 o = make_uint4(*(unsigned*)&h01, *(unsigned*)&h23,
                         *(unsigned*)&h45, *(unsigned*)&h67);
    *(uint4*)(q + n * HID + j0) = o;
}

// -------- proj: q = a[N,32] @ W[32,32]  (fp16 in, fp16 out) --------
__global__ __launch_bounds__(256)
void proj_kernel(const __half* __restrict__ a, const float* __restrict__ W,
                 __half* __restrict__ q) {
    __shared__ float Ws[HID * HID];
    int tid = threadIdx.x;
    for (int i = tid; i < HID * HID; i += 256) Ws[i] = W[i];
    __syncthreads();

    int n = blockIdx.x * 64 + (tid >> 2);
    int j0 = (tid & 3) * 8;
    const uint4* ar = (const uint4*)(a + n * HID);   // 4 x uint4 = 32 fp16
    float av[32];
#pragma unroll
    for (int t = 0; t < 4; t++) {
        uint4 v = __ldg(&ar[t]);
        float2 f0 = __half22float2(*reinterpret_cast<__half2*>(&v.x));
        float2 f1 = __half22float2(*reinterpret_cast<__half2*>(&v.y));
        float2 f2 = __half22float2(*reinterpret_cast<__half2*>(&v.z));
        float2 f3 = __half22float2(*reinterpret_cast<__half2*>(&v.w));
        av[t * 8 + 0] = f0.x; av[t * 8 + 1] = f0.y;
        av[t * 8 + 2] = f1.x; av[t * 8 + 3] = f1.y;
        av[t * 8 + 4] = f2.x; av[t * 8 + 5] = f2.y;
        av[t * 8 + 6] = f3.x; av[t * 8 + 7] = f3.y;
    }
    float acc[8] = {0.f, 0.f, 0.f, 0.f, 0.f, 0.f, 0.f, 0.f};
#pragma unroll
    for (int k = 0; k < HID; k++) {
        float ak = av[k];
#pragma unroll
        for (int j = 0; j < 8; j++)
            acc[j] = fmaf(ak, Ws[k * HID + j0 + j], acc[j]);
    }
    __half2 h01 = __float22half2_rn(make_float2(acc[0], acc[1]));
    __half2 h23 = __float22half2_rn(make_float2(acc[2], acc[3]));
    __half2 h45 = __float22half2_rn(make_float2(acc[4], acc[5]));
    __half2 h67 = __float22half2_rn(make_float2(acc[6], acc[7]));
    uint4 o = make_uint4(*(unsigned*)&h01, *(unsigned*)&h23,
                         *(unsigned*)&h45, *(unsigned*)&h67);
    *(uint4*)(q + n * HID + j0) = o;
}

// Convert a uint4 of 8 fp16 values and FMA into 8 fp32 accumulators.
__device__ __forceinline__ void h8_fma(float* acc, uint4 v, float w) {
    float2 f0 = __half22float2(*reinterpret_cast<__half2*>(&v.x));
    float2 f1 = __half22float2(*reinterpret_cast<__half2*>(&v.y));
    float2 f2 = __half22float2(*reinterpret_cast<__half2*>(&v.z));
    float2 f3 = __half22float2(*reinterpret_cast<__half2*>(&v.w));
    acc[0] = fmaf(f0.x, w, acc[0]);
    acc[1] = fmaf(f0.y, w, acc[1]);
    acc[2] = fmaf(f1.x, w, acc[2]);
    acc[3] = fmaf(f1.y, w, acc[3]);
    acc[4] = fmaf(f2.x, w, acc[4]);
    acc[5] = fmaf(f2.y, w, acc[5]);
    acc[6] = fmaf(f3.x, w, acc[6]);
    acc[7] = fmaf(f3.y, w, acc[7]);
}

// -------- agg: out[n] = elu(sum_e w_e q[src_e] + b)  (no linear — pre-projected) --------
// c0 = lane&3 owns channels 8c0..8c0+7; g = lane>>2 owns one of 8 edge slots.
// After the xor reduction lanes 0..3 (g==0) hold all 32 channels and store.
template <bool OUT_HALF>
__global__ __launch_bounds__(256)
void agg_kernel(const __half* __restrict__ q,
                const float* __restrict__ b,
                __half* __restrict__ outh,
                float* __restrict__ outf) {
    __shared__ float bs[HID];
    int tid = threadIdx.x;
    if (tid < HID) bs[tid] = b[tid];
    __syncthreads();

    int n = blockIdx.x * 8 + (tid >> 5);
    int lane = tid & 31;
    int c0 = lane & 3;
    int g = lane >> 2;
    int cnt = g_cnt[n];
    if (cnt > SLOTS) cnt = SLOTS;
    int e0 = n * SLOTS;
    int e1 = e0 + cnt;

    float acc[8] = {0.f, 0.f, 0.f, 0.f, 0.f, 0.f, 0.f, 0.f};
    const uint4* h4 = (const uint4*)q;    // row n = h4[n*4 .. n*4+3]

    for (int base = e0; base < e1; base += 32) {
        float2 es[4];
#pragma unroll
        for (int j = 0; j < 4; j++) {
            int idx = base + 8 * j + g;
            es[j] = (idx < e1) ? __ldg(&g_es[idx]) : make_float2(0.0f, 0.0f);
        }
#pragma unroll
        for (int j = 0; j < 4; j++) {
            uint4 v = __ldg(&h4[__float_as_int(es[j].x) * 4 + c0]);
            h8_fma(acc, v, es[j].y);
        }
    }

    // reduce over the 8 edge-slot groups (same c0: xor bits 2..4)
#pragma unroll
    for (int off = 4; off <= 16; off <<= 1) {
#pragma unroll
        for (int i = 0; i < 8; i++)
            acc[i] += __shfl_xor_sync(0xffffffffu, acc[i], off);
    }

    if (g == 0) {   // lanes 0..3: bias + elu + store 8 channels each
        float r[8];
#pragma unroll
        for (int i = 0; i < 8; i++) r[i] = elu(acc[i] + bs[c0 * 8 + i]);
        if (OUT_HALF) {
            __half2 h01 = __float22half2_rn(make_float2(r[0], r[1]));
            __half2 h23 = __float22half2_rn(make_float2(r[2], r[3]));
            __half2 h45 = __float22half2_rn(make_float2(r[4], r[5]));
            __half2 h67 = __float22half2_rn(make_float2(r[6], r[7]));
            uint4 o = make_uint4(*(unsigned*)&h01, *(unsigned*)&h23,
                                 *(unsigned*)&h45, *(unsigned*)&h67);
            *(uint4*)(outh + n * HID + c0 * 8) = o;
        } else {
            float4* op = (float4*)(outf + n * HID + c0 * 8);
            op[0] = make_float4(r[0], r[1], r[2], r[3]);
            op[1] = make_float4(r[4], r[5], r[6], r[7]);
        }
    }
}

// -------- FC1 with packed f32x2 FMA: g_fc1 += H @ Wfc1; resets g_cnt --------
__global__ __launch_bounds__(256)
void fc1_kernel(const float* __restrict__ H, const float* __restrict__ Wfc1) {
    // reset bucket counters for the next graph replay (512 blocks * 256 >= N)
    int gid = blockIdx.x * 256 + threadIdx.x;
    if (gid < N_NODES) g_cnt[gid] = 0;

    __shared__ float Hs[TILE_K * N_GRAPHS];   // [k][m] layout, 16 KB
    int tid = threadIdx.x;
    int k0 = blockIdx.x * TILE_K;

    for (int i = tid; i < TILE_K * N_GRAPHS; i += 256) {
        int m = i / TILE_K;
        int k = i - m * TILE_K;
        Hs[k * N_GRAPHS + m] = H[m * K_FC + k0 + k];   // coalesced global read
    }
    __syncthreads();

    unsigned long long acc2[8];
#pragma unroll
    for (int i = 0; i < 8; i++) acc2[i] = 0ULL;

    for (int k = 0; k < TILE_K; k++) {
        float wv = __ldg(&Wfc1[(k0 + k) * FC_HID + tid]);     // coalesced
        unsigned long long wv2;
        unsigned int wu = __float_as_uint(wv);
        asm("mov.b64 %0, {%1, %2};" : "=l"(wv2) : "r"(wu), "r"(wu));
        const ulonglong2* hp = (const ulonglong2*)&Hs[k * N_GRAPHS];
        ulonglong2 p0 = hp[0], p1 = hp[1], p2 = hp[2], p3 = hp[3];
        FMA_F32X2(acc2[0], p0.x, wv2, acc2[0]);
        FMA_F32X2(acc2[1], p0.y, wv2, acc2[1]);
        FMA_F32X2(acc2[2], p1.x, wv2, acc2[2]);
        FMA_F32X2(acc2[3], p1.y, wv2, acc2[3]);
        FMA_F32X2(acc2[4], p2.x, wv2, acc2[4]);
        FMA_F32X2(acc2[5], p2.y, wv2, acc2[5]);
        FMA_F32X2(acc2[6], p3.x, wv2, acc2[6]);
        FMA_F32X2(acc2[7], p3.y, wv2, acc2[7]);
    }
#pragma unroll
    for (int i = 0; i < 8; i++) {
        unsigned int lo, hi;
        asm("mov.b64 {%0, %1}, %2;" : "=r"(lo), "=r"(hi) : "l"(acc2[i]));
        atomicAdd(&g_fc1[(2 * i)     * FC_HID + tid], __uint_as_float(lo));
        atomicAdd(&g_fc1[(2 * i + 1) * FC_HID + tid], __uint_as_float(hi));
    }
}

// -------- FC2: out[16,64] = elu(g_fc1 + bfc1) @ Wfc2 + bfc2 --------
__global__ __launch_bounds__(1024)
void fc2_kernel(const float* __restrict__ bfc1,
                const float* __restrict__ Wfc2,
                const float* __restrict__ bfc2,
                float* __restrict__ out) {
    __shared__ float s[N_GRAPHS * FC_HID];   // 16 KB
    int tid = threadIdx.x;
    for (int i = tid; i < N_GRAPHS * FC_HID; i += 1024) {
        float v = g_fc1[i] + bfc1[i & (FC_HID - 1)];
        s[i] = elu(v);
    }
    __syncthreads();

    int m = tid >> 6;
    int j = tid & 63;
    float acc = bfc2[j];
#pragma unroll 8
    for (int k = 0; k < FC_HID; k++)
        acc = fmaf(s[m * FC_HID + k], __ldg(&Wfc2[k * LATENT + j]), acc);
    out[m * LATENT + j] = acc;
}

extern "C" void kernel_launch(void* const* d_in, const int* in_sizes, int n_in,
                              void* d_out, int out_size) {
    // ---- size-based input mapping (ordering-agnostic) ----
    const float *x = 0, *ea = 0, *W1 = 0, *Wfc1 = 0, *bfc1 = 0, *Wfc2 = 0, *bfc2 = 0;
    const float *Wh[2] = {0, 0};       // W2, W3 (both 1024 elems, relative order kept)
    const float *bh[3] = {0, 0, 0};    // b1, b2, b3 (all 32 elems, relative order kept)
    const void  *ei = 0;
    int nWh = 0, nbh = 0;
    for (int i = 0; i < n_in; i++) {
        switch (in_sizes[i]) {
            case 1048576:  x    = (const float*)d_in[i]; break;  // 65536*16
            case 2097152:  ea   = (const float*)d_in[i]; break;  // E
            case 512:      W1   = (const float*)d_in[i]; break;  // 16*32
            case 1024:     if (nWh < 2) Wh[nWh++] = (const float*)d_in[i]; break;
            case 32:       if (nbh < 3) bh[nbh++] = (const float*)d_in[i]; break;
            case 33554432: Wfc1 = (const float*)d_in[i]; break;  // 131072*256
            case 256:      bfc1 = (const float*)d_in[i]; break;
            case 16384:    Wfc2 = (const float*)d_in[i]; break;  // 256*64
            case 64:       bfc2 = (const float*)d_in[i]; break;
            case 4194304:  ei   = d_in[i]; break;                // 2*E
            default: break;
        }
    }
    const float *W2 = Wh[0], *W3 = Wh[1];
    const float *b1 = bh[0], *b2 = bh[1], *b3 = bh[2];
    float* out = (float*)d_out;

    void *qp, *ap, *h3p;
    cudaGetSymbolAddress(&qp, g_q);
    cudaGetSymbolAddress(&ap, g_a);
    cudaGetSymbolAddress(&h3p, g_h3);
    __half* q = (__half*)qp;
    __half* a = (__half*)ap;
    float*  h3 = (float*)h3p;

    // ---- single-pass bucket CSR; g_cnt reset by fc1 ----
    fill_kernel<<<E_EDGES / 512, 256>>>((const unsigned int*)ei, ea);      // 1

    // ---- layer 1 (pre-projected): q0 = x@W1 ; a1 = elu(agg(q0)+b1) ----
    proj0_kernel<<<N_NODES / 64, 256>>>(x, W1, q);                         // 2
    agg_kernel<true><<<N_NODES / 8, 256>>>(q, b1, a, 0);                   // 3

    // ---- layer 2: q1 = a1@W2 ; a2 = elu(agg(q1)+b2) ----
    proj_kernel<<<N_NODES / 64, 256>>>(a, W2, q);                          // 4
    agg_kernel<true><<<N_NODES / 8, 256>>>(q, b2, a, 0);                   // 5

    // ---- layer 3: q2 = a2@W3 ; h3 = elu(agg(q2)+b3) (fp32) ----
    proj_kernel<<<N_NODES / 64, 256>>>(a, W3, q);                          // 6
    agg_kernel<false><<<N_NODES / 8, 256>>>(q, b3, 0, h3);                 // 7

    // ---- FC1 (g_fc1 pre-zeroed by fill; resets g_cnt) ----
    fc1_kernel<<<K_FC / TILE_K, 256>>>(h3, Wfc1);                          // 8

    // ---- FC2 -> output ----
    fc2_kernel<<<1, 1024>>>(bfc1, Wfc2, bfc2, out);                        // 9
}

// round 12
// speedup vs baseline: 1.1180x; 1.1180x over previous
#include <cuda_runtime.h>
#include <cuda_fp16.h>
#include <math.h>

#define N_NODES   65536
#define E_EDGES   2097152
#define FEAT_IN   16
#define HID       32
#define N_GRAPHS  16
#define K_FC      131072      // 4096 * 32
#define FC_HID    256
#define LATENT    64
#define TILE_K    256
#define SLOTS     96          // bucket capacity per node; P(Poisson(32) > 96) ~ 1e-18

// Packed fp32x2 FMA (sm_103a FFMA2) — only reachable via PTX fma.rn.f32x2.
#define FMA_F32X2(d, a, b, c) \
    asm("fma.rn.f32x2 %0, %1, %2, %3;" : "=l"(d) : "l"(a), "l"(b), "l"(c))

// -------- scratch (static device globals; no runtime allocation) --------
__device__ float2 g_es[N_NODES * SLOTS];   // bucketed (src_bits, w); 48MB
__device__ int    g_cnt[N_NODES];          // zero-init; reset by fc1 each call
__device__ __half g_xh[N_NODES * FEAT_IN]; // fp16 copy of x (2MB)
__device__ __half g_hAh[N_NODES * HID];    // fp16 layer-1 output (4MB)
__device__ __half g_hBh[N_NODES * HID];    // fp16 layer-2 output (4MB)
__device__ float  g_hA[N_NODES * HID];     // fp32 layer-3 output (for FC1)
__device__ float  g_fc1[N_GRAPHS * FC_HID]; // zeroed by fill_kernel each call

__device__ __forceinline__ float elu(float v) {
    return v > 0.0f ? v : expm1f(v);
}

// Per-block dtype self-detection: if buffer is int64, hi-words of the first 32
// entries are all zero (indices < 65536); for int32 data they're random indices.
__device__ __forceinline__ int block_detect_is64(const unsigned int* ei32, int* s_is64) {
    if (threadIdx.x < 32) {
        unsigned int hi = ei32[threadIdx.x * 2 + 1];
        unsigned int ball = __ballot_sync(0xffffffffu, hi != 0u);
        if (threadIdx.x == 0) *s_is64 = (ball == 0u) ? 1 : 0;
    }
    __syncthreads();
    return *s_is64;
}

// -------- single-pass bucket fill (1 edge/thread) + x->fp16 + g_fc1 reset --------
__global__ __launch_bounds__(256)
void fill_kernel(const unsigned int* __restrict__ ei32, const float* __restrict__ w,
                 const float* __restrict__ x) {
    __shared__ int s_is64;
    int is64 = block_detect_is64(ei32, &s_is64);
    if (blockIdx.x == 0) {
        for (int i = threadIdx.x; i < N_GRAPHS * FC_HID; i += 256) g_fc1[i] = 0.0f;
    }
    long long e = (long long)blockIdx.x * 256 + threadIdx.x;
    // x -> half: first 4096 blocks convert exactly N*16 elements
    if (e < (long long)N_NODES * FEAT_IN) g_xh[e] = __float2half(x[e]);

    int s = is64 ? (int)ei32[2 * e]             : (int)ei32[e];
    int d = is64 ? (int)ei32[2 * (E_EDGES + e)] : (int)ei32[E_EDGES + e];
    float wv = w[e];
    int p = atomicAdd(&g_cnt[d], 1);
    if (p < SLOTS) g_es[d * SLOTS + p] = make_float2(__int_as_float(s), wv);
}

// Convert a uint4 of 8 fp16 values and FMA into 8 fp32 accumulators.
__device__ __forceinline__ void h8_fma(float* acc, uint4 v, float w) {
    float2 f0 = __half22float2(*reinterpret_cast<__half2*>(&v.x));
    float2 f1 = __half22float2(*reinterpret_cast<__half2*>(&v.y));
    float2 f2 = __half22float2(*reinterpret_cast<__half2*>(&v.z));
    float2 f3 = __half22float2(*reinterpret_cast<__half2*>(&v.w));
    acc[0] = fmaf(f0.x, w, acc[0]);
    acc[1] = fmaf(f0.y, w, acc[1]);
    acc[2] = fmaf(f1.x, w, acc[2]);
    acc[3] = fmaf(f1.y, w, acc[3]);
    acc[4] = fmaf(f2.x, w, acc[4]);
    acc[5] = fmaf(f2.y, w, acc[5]);
    acc[6] = fmaf(f3.x, w, acc[6]);
    acc[7] = fmaf(f3.y, w, acc[7]);
}

// -------- fused agg + linear + ELU, CIN=32: 4 nodes/warp, W in registers --------
// c0 = lane&3 owns channels 8c0..8c0+7 of the gather; g = lane>>2 = edge slot.
// Epilogue per node: shfl-broadcast agg + FFMA against register-resident W column
// (lane j holds W[:,j]) — ZERO shared loads per node.
template <bool OUT_HALF>
__global__ __launch_bounds__(256)
void agg_linear32h_kernel(const __half* __restrict__ h,
                          const float* __restrict__ W,
                          const float* __restrict__ b,
                          __half* __restrict__ outh,
                          float* __restrict__ outf) {
    int tid = threadIdx.x;
    int lane = tid & 31;
    int wid = tid >> 5;

    float Wreg[HID];
#pragma unroll
    for (int k = 0; k < HID; k++) Wreg[k] = __ldg(&W[k * HID + lane]);  // coalesced
    float breg = __ldg(&b[lane]);

    int c0 = lane & 3;
    int g = lane >> 2;
    const uint4* h4 = (const uint4*)h;    // row n = h4[n*4 .. n*4+3]

#pragma unroll
    for (int nn = 0; nn < 4; nn++) {
        int n = blockIdx.x * 32 + wid * 4 + nn;
        int cnt = g_cnt[n];
        if (cnt > SLOTS) cnt = SLOTS;
        int e0 = n * SLOTS;
        int e1 = e0 + cnt;

        float acc[8] = {0.f, 0.f, 0.f, 0.f, 0.f, 0.f, 0.f, 0.f};
        for (int base = e0; base < e1; base += 32) {
            float2 es[4];
#pragma unroll
            for (int j = 0; j < 4; j++) {
                int idx = base + 8 * j + g;
                es[j] = (idx < e1) ? __ldg(&g_es[idx]) : make_float2(0.0f, 0.0f);
            }
#pragma unroll
            for (int j = 0; j < 4; j++) {
                uint4 v = __ldg(&h4[__float_as_int(es[j].x) * 4 + c0]);
                h8_fma(acc, v, es[j].y);
            }
        }

        // reduce over the 8 edge-slot groups (same c0: xor bits 2..4)
#pragma unroll
        for (int off = 4; off <= 16; off <<= 1) {
#pragma unroll
            for (int i = 0; i < 8; i++)
                acc[i] += __shfl_xor_sync(0xffffffffu, acc[i], off);
        }

        // in-warp linear vs register W: agg chan k lives in acc[k&7] of lane (k>>3)
        float o = breg;
#pragma unroll
        for (int k = 0; k < HID; k++) {
            float ak = __shfl_sync(0xffffffffu, acc[k & 7], k >> 3);
            o = fmaf(ak, Wreg[k], o);
        }
        float r = elu(o);
        if (OUT_HALF) outh[n * HID + lane] = __float2half(r);
        else          outf[n * HID + lane] = r;
    }
}

// -------- fused agg + linear + ELU, CIN=16: 4 nodes/warp, W in registers --------
__global__ __launch_bounds__(256)
void agg_linear16h_kernel(const __half* __restrict__ xh,
                          const float* __restrict__ W,
                          const float* __restrict__ b,
                          __half* __restrict__ out) {
    int tid = threadIdx.x;
    int lane = tid & 31;
    int wid = tid >> 5;

    float Wreg[FEAT_IN];
#pragma unroll
    for (int k = 0; k < FEAT_IN; k++) Wreg[k] = __ldg(&W[k * HID + lane]);
    float breg = __ldg(&b[lane]);

    int c0 = lane & 1;
    int g = lane >> 1;
    const uint4* x4 = (const uint4*)xh;   // row n = x4[n*2 .. n*2+1]

#pragma unroll
    for (int nn = 0; nn < 4; nn++) {
        int n = blockIdx.x * 32 + wid * 4 + nn;
        int cnt = g_cnt[n];
        if (cnt > SLOTS) cnt = SLOTS;
        int e0 = n * SLOTS;
        int e1 = e0 + cnt;

        float acc[8] = {0.f, 0.f, 0.f, 0.f, 0.f, 0.f, 0.f, 0.f};
        for (int base = e0; base < e1; base += 32) {
            float2 es[2];
#pragma unroll
            for (int j = 0; j < 2; j++) {
                int idx = base + 16 * j + g;
                es[j] = (idx < e1) ? __ldg(&g_es[idx]) : make_float2(0.0f, 0.0f);
            }
#pragma unroll
            for (int j = 0; j < 2; j++) {
                uint4 v = __ldg(&x4[__float_as_int(es[j].x) * 2 + c0]);
                h8_fma(acc, v, es[j].y);
            }
        }

        // reduce over the 16 edge-slot groups (same c0: xor bits 1..4)
#pragma unroll
        for (int off = 2; off <= 16; off <<= 1) {
#pragma unroll
            for (int i = 0; i < 8; i++)
                acc[i] += __shfl_xor_sync(0xffffffffu, acc[i], off);
        }

        // in-warp linear: agg chan k (0..15) lives in acc[k&7] of lane (k>>3)
        float o = breg;
#pragma unroll
        for (int k = 0; k < FEAT_IN; k++) {
            float ak = __shfl_sync(0xffffffffu, acc[k & 7], k >> 3);
            o = fmaf(ak, Wreg[k], o);
        }
        out[n * HID + lane] = __float2half(elu(o));
    }
}

// -------- FC1 with packed f32x2 FMA: g_fc1 += H @ Wfc1; resets g_cnt --------
__global__ __launch_bounds__(256)
void fc1_kernel(const float* __restrict__ H, const float* __restrict__ Wfc1) {
    // reset bucket counters for the next graph replay (512 blocks * 256 >= N)
    int gid = blockIdx.x * 256 + threadIdx.x;
    if (gid < N_NODES) g_cnt[gid] = 0;

    __shared__ float Hs[TILE_K * N_GRAPHS];   // [k][m] layout, 16 KB
    int tid = threadIdx.x;
    int k0 = blockIdx.x * TILE_K;

    for (int i = tid; i < TILE_K * N_GRAPHS; i += 256) {
        int m = i / TILE_K;
        int k = i - m * TILE_K;
        Hs[k * N_GRAPHS + m] = H[m * K_FC + k0 + k];   // coalesced global read
    }
    __syncthreads();

    unsigned long long acc2[8];
#pragma unroll
    for (int i = 0; i < 8; i++) acc2[i] = 0ULL;

    for (int k = 0; k < TILE_K; k++) {
        float wv = __ldg(&Wfc1[(k0 + k) * FC_HID + tid]);     // coalesced
        unsigned long long wv2;
        unsigned int wu = __float_as_uint(wv);
        asm("mov.b64 %0, {%1, %2};" : "=l"(wv2) : "r"(wu), "r"(wu));
        const ulonglong2* hp = (const ulonglong2*)&Hs[k * N_GRAPHS];
        ulonglong2 p0 = hp[0], p1 = hp[1], p2 = hp[2], p3 = hp[3];
        FMA_F32X2(acc2[0], p0.x, wv2, acc2[0]);
        FMA_F32X2(acc2[1], p0.y, wv2, acc2[1]);
        FMA_F32X2(acc2[2], p1.x, wv2, acc2[2]);
        FMA_F32X2(acc2[3], p1.y, wv2, acc2[3]);
        FMA_F32X2(acc2[4], p2.x, wv2, acc2[4]);
        FMA_F32X2(acc2[5], p2.y, wv2, acc2[5]);
        FMA_F32X2(acc2[6], p3.x, wv2, acc2[6]);
        FMA_F32X2(acc2[7], p3.y, wv2, acc2[7]);
    }
#pragma unroll
    for (int i = 0; i < 8; i++) {
        unsigned int lo, hi;
        asm("mov.b64 {%0, %1}, %2;" : "=r"(lo), "=r"(hi) : "l"(acc2[i]));
        atomicAdd(&g_fc1[(2 * i)     * FC_HID + tid], __uint_as_float(lo));
        atomicAdd(&g_fc1[(2 * i + 1) * FC_HID + tid], __uint_as_float(hi));
    }
}

// -------- FC2: out[16,64] = elu(g_fc1 + bfc1) @ Wfc2 + bfc2 --------
__global__ __launch_bounds__(1024)
void fc2_kernel(const float* __restrict__ bfc1,
                const float* __restrict__ Wfc2,
                const float* __restrict__ bfc2,
                float* __restrict__ out) {
    __shared__ float s[N_GRAPHS * FC_HID];   // 16 KB
    int tid = threadIdx.x;
    for (int i = tid; i < N_GRAPHS * FC_HID; i += 1024) {
        float v = g_fc1[i] + bfc1[i & (FC_HID - 1)];
        s[i] = elu(v);
    }
    __syncthreads();

    int m = tid >> 6;
    int j = tid & 63;
    float acc = bfc2[j];
#pragma unroll 8
    for (int k = 0; k < FC_HID; k++)
        acc = fmaf(s[m * FC_HID + k], __ldg(&Wfc2[k * LATENT + j]), acc);
    out[m * LATENT + j] = acc;
}

extern "C" void kernel_launch(void* const* d_in, const int* in_sizes, int n_in,
                              void* d_out, int out_size) {
    // ---- size-based input mapping (ordering-agnostic) ----
    const float *x = 0, *ea = 0, *W1 = 0, *Wfc1 = 0, *bfc1 = 0, *Wfc2 = 0, *bfc2 = 0;
    const float *Wh[2] = {0, 0};       // W2, W3 (both 1024 elems, relative order kept)
    const float *bh[3] = {0, 0, 0};    // b1, b2, b3 (all 32 elems, relative order kept)
    const void  *ei = 0;
    int nWh = 0, nbh = 0;
    for (int i = 0; i < n_in; i++) {
        switch (in_sizes[i]) {
            case 1048576:  x    = (const float*)d_in[i]; break;  // 65536*16
            case 2097152:  ea   = (const float*)d_in[i]; break;  // E
            case 512:      W1   = (const float*)d_in[i]; break;  // 16*32
            case 1024:     if (nWh < 2) Wh[nWh++] = (const float*)d_in[i]; break;
            case 32:       if (nbh < 3) bh[nbh++] = (const float*)d_in[i]; break;
            case 33554432: Wfc1 = (const float*)d_in[i]; break;  // 131072*256
            case 256:      bfc1 = (const float*)d_in[i]; break;
            case 16384:    Wfc2 = (const float*)d_in[i]; break;  // 256*64
            case 64:       bfc2 = (const float*)d_in[i]; break;
            case 4194304:  ei   = d_in[i]; break;                // 2*E
            default: break;
        }
    }
    const float *W2 = Wh[0], *W3 = Wh[1];
    const float *b1 = bh[0], *b2 = bh[1], *b3 = bh[2];
    float* out = (float*)d_out;

    void *xhp, *hAhp, *hBhp, *hAp;
    cudaGetSymbolAddress(&xhp, g_xh);
    cudaGetSymbolAddress(&hAhp, g_hAh);
    cudaGetSymbolAddress(&hBhp, g_hBh);
    cudaGetSymbolAddress(&hAp, g_hA);

    // ---- single-pass bucket CSR + x->fp16; g_cnt reset by fc1 ----
    fill_kernel<<<E_EDGES / 256, 256>>>((const unsigned int*)ei, ea, x);   // 1

    // ---- layer 1: xh[N,16] -> hAh[N,32] (fp16) ----
    agg_linear16h_kernel<<<N_NODES / 32, 256>>>((const __half*)xhp, W1, b1,
                                                (__half*)hAhp);            // 2
    // ---- layer 2: hAh -> hBh (fp16) ----
    agg_linear32h_kernel<true><<<N_NODES / 32, 256>>>((const __half*)hAhp, W2, b2,
                                                      (__half*)hBhp, 0);   // 3
    // ---- layer 3: hBh -> hA (fp32, for FC1) ----  (4th launch — profiled)
    agg_linear32h_kernel<false><<<N_NODES / 32, 256>>>((const __half*)hBhp, W3, b3,
                                                       0, (float*)hAp);    // 4

    // ---- FC1 (g_fc1 pre-zeroed by fill; resets g_cnt) ----
    fc1_kernel<<<K_FC / TILE_K, 256>>>((const float*)hAp, Wfc1);           // 5

    // ---- FC2 -> output ----
    fc2_kernel<<<1, 1024>>>(bfc1, Wfc2, bfc2, out);                        // 6
}

// round 13
// speedup vs baseline: 1.1340x; 1.0143x over previous
#include <cuda_runtime.h>
#include <cuda_fp16.h>
#include <math.h>

#define N_NODES   65536
#define E_EDGES   2097152
#define FEAT_IN   16
#define HID       32
#define N_GRAPHS  16
#define K_FC      131072      // 4096 * 32
#define FC_HID    256
#define LATENT    64
#define TILE_K    256
#define SLOTS     96          // bucket capacity per node; P(Poisson(32) > 96) ~ 1e-18

// Packed fp32x2 ops (sm_103a) — only reachable via PTX.
#define FMA_F32X2(d, a, b, c) \
    asm("fma.rn.f32x2 %0, %1, %2, %3;" : "=l"(d) : "l"(a), "l"(b), "l"(c))
#define ADD_F32X2(d, a, b) \
    asm("add.rn.f32x2 %0, %1, %2;" : "=l"(d) : "l"(a), "l"(b))

// -------- scratch (static device globals; no runtime allocation) --------
__device__ float2 g_es[N_NODES * SLOTS];   // bucketed (src_bits, w); 48MB
__device__ int    g_cnt[N_NODES];          // zero-init; reset by fc1 each call
__device__ __half g_xh[N_NODES * FEAT_IN]; // fp16 copy of x (2MB)
__device__ __half g_hAh[N_NODES * HID];    // fp16 layer-1 output (4MB)
__device__ __half g_hBh[N_NODES * HID];    // fp16 layer-2 output (4MB)
__device__ float  g_hA[N_NODES * HID];     // fp32 layer-3 output (for FC1)
__device__ float  g_fc1[N_GRAPHS * FC_HID]; // zeroed by fill_kernel each call

__device__ __forceinline__ float elu(float v) {
    return v > 0.0f ? v : expm1f(v);
}

// Per-block dtype self-detection: if buffer is int64, hi-words of the first 32
// entries are all zero (indices < 65536); for int32 data they're random indices.
__device__ __forceinline__ int block_detect_is64(const unsigned int* ei32, int* s_is64) {
    if (threadIdx.x < 32) {
        unsigned int hi = ei32[threadIdx.x * 2 + 1];
        unsigned int ball = __ballot_sync(0xffffffffu, hi != 0u);
        if (threadIdx.x == 0) *s_is64 = (ball == 0u) ? 1 : 0;
    }
    __syncthreads();
    return *s_is64;
}

// -------- single-pass bucket fill (1 edge/thread) + x->fp16 + g_fc1 reset --------
__global__ __launch_bounds__(256)
void fill_kernel(const unsigned int* __restrict__ ei32, const float* __restrict__ w,
                 const float* __restrict__ x) {
    __shared__ int s_is64;
    int is64 = block_detect_is64(ei32, &s_is64);
    if (blockIdx.x == 0) {
        for (int i = threadIdx.x; i < N_GRAPHS * FC_HID; i += 256) g_fc1[i] = 0.0f;
    }
    long long e = (long long)blockIdx.x * 256 + threadIdx.x;
    // x -> half: first 4096 blocks convert exactly N*16 elements
    if (e < (long long)N_NODES * FEAT_IN) g_xh[e] = __float2half(x[e]);

    int s = is64 ? (int)ei32[2 * e]             : (int)ei32[e];
    int d = is64 ? (int)ei32[2 * (E_EDGES + e)] : (int)ei32[E_EDGES + e];
    float wv = w[e];
    int p = atomicAdd(&g_cnt[d], 1);
    if (p < SLOTS) g_es[d * SLOTS + p] = make_float2(__int_as_float(s), wv);
}

// Convert a uint4 of 8 fp16 values and FFMA2 into 4 packed f32x2 accumulators.
__device__ __forceinline__ void h8_fma2(unsigned long long* acc2, uint4 v,
                                        unsigned long long wv2) {
    float2 f0 = __half22float2(*reinterpret_cast<__half2*>(&v.x));
    float2 f1 = __half22float2(*reinterpret_cast<__half2*>(&v.y));
    float2 f2 = __half22float2(*reinterpret_cast<__half2*>(&v.z));
    float2 f3 = __half22float2(*reinterpret_cast<__half2*>(&v.w));
    FMA_F32X2(acc2[0], *(unsigned long long*)&f0, wv2, acc2[0]);
    FMA_F32X2(acc2[1], *(unsigned long long*)&f1, wv2, acc2[1]);
    FMA_F32X2(acc2[2], *(unsigned long long*)&f2, wv2, acc2[2]);
    FMA_F32X2(acc2[3], *(unsigned long long*)&f3, wv2, acc2[3]);
}

__device__ __forceinline__ unsigned long long pack_w2(float w) {
    unsigned long long w2;
    unsigned int wu = __float_as_uint(w);
    asm("mov.b64 %0, {%1, %2};" : "=l"(w2) : "r"(wu), "r"(wu));
    return w2;
}

// -------- fused agg + linear + ELU, CIN=32 (R10 structure + f32x2) --------
// c0 = lane&3 owns channels 8c0..8c0+7; g = lane>>2 owns one of 8 edge slots.
template <bool OUT_HALF>
__global__ __launch_bounds__(256)
void agg_linear32h_kernel(const __half* __restrict__ h,
                          const float* __restrict__ W,
                          const float* __restrict__ b,
                          __half* __restrict__ outh,
                          float* __restrict__ outf) {
    __shared__ float Ws[HID * HID];
    __shared__ float bs[HID];
    int tid = threadIdx.x;
    for (int i = tid; i < HID * HID; i += 256) Ws[i] = W[i];
    if (tid < HID) bs[tid] = b[tid];
    __syncthreads();

    int n = blockIdx.x * 8 + (tid >> 5);
    int lane = tid & 31;
    int c0 = lane & 3;
    int g = lane >> 2;
    int cnt = g_cnt[n];
    if (cnt > SLOTS) cnt = SLOTS;
    int e0 = n * SLOTS;
    int e1 = e0 + cnt;

    unsigned long long acc2[4] = {0ULL, 0ULL, 0ULL, 0ULL};
    const uint4* h4 = (const uint4*)h;    // row n = h4[n*4 .. n*4+3]

    for (int base = e0; base < e1; base += 32) {
        float2 es[4];
#pragma unroll
        for (int j = 0; j < 4; j++) {
            int idx = base + 8 * j + g;
            es[j] = (idx < e1) ? __ldg(&g_es[idx]) : make_float2(0.0f, 0.0f);
        }
#pragma unroll
        for (int j = 0; j < 4; j++) {
            uint4 v = __ldg(&h4[__float_as_int(es[j].x) * 4 + c0]);
            h8_fma2(acc2, v, pack_w2(es[j].y));
        }
    }

    // reduce over the 8 edge-slot groups (same c0: xor bits 2..4), packed adds
#pragma unroll
    for (int off = 4; off <= 16; off <<= 1) {
#pragma unroll
        for (int i = 0; i < 4; i++) {
            unsigned long long t = __shfl_xor_sync(0xffffffffu, acc2[i], off);
            ADD_F32X2(acc2[i], acc2[i], t);
        }
    }

    // unpack: agg channel k lives in accf[k&7] of lane (k>>3)
    float accf[8];
#pragma unroll
    for (int i = 0; i < 4; i++) {
        unsigned int lo, hi;
        asm("mov.b64 {%0, %1}, %2;" : "=r"(lo), "=r"(hi) : "l"(acc2[i]));
        accf[2 * i]     = __uint_as_float(lo);
        accf[2 * i + 1] = __uint_as_float(hi);
    }

    // in-warp linear: out[n][lane] = b[lane] + sum_k agg_k * W[k][lane]
    float o = bs[lane];
#pragma unroll
    for (int k = 0; k < HID; k++) {
        float ak = __shfl_sync(0xffffffffu, accf[k & 7], k >> 3);
        o = fmaf(ak, Ws[k * HID + lane], o);
    }
    float r = elu(o);
    if (OUT_HALF) outh[n * HID + lane] = __float2half(r);
    else          outf[n * HID + lane] = r;
}

// -------- fused agg + linear + ELU, CIN=16 (R10 structure + f32x2) --------
// c0 = lane&1 owns channels 8c0..8c0+7; g = lane>>1 owns one of 16 edge slots.
__global__ __launch_bounds__(256)
void agg_linear16h_kernel(const __half* __restrict__ xh,
                          const float* __restrict__ W,
                          const float* __restrict__ b,
                          __half* __restrict__ out) {
    __shared__ float Ws[FEAT_IN * HID];
    __shared__ float bs[HID];
    int tid = threadIdx.x;
    for (int i = tid; i < FEAT_IN * HID; i += 256) Ws[i] = W[i];
    if (tid < HID) bs[tid] = b[tid];
    __syncthreads();

    int n = blockIdx.x * 8 + (tid >> 5);
    int lane = tid & 31;
    int c0 = lane & 1;
    int g = lane >> 1;
    int cnt = g_cnt[n];
    if (cnt > SLOTS) cnt = SLOTS;
    int e0 = n * SLOTS;
    int e1 = e0 + cnt;

    unsigned long long acc2[4] = {0ULL, 0ULL, 0ULL, 0ULL};
    const uint4* x4 = (const uint4*)xh;   // row n = x4[n*2 .. n*2+1]

    for (int base = e0; base < e1; base += 32) {
        float2 es[2];
#pragma unroll
        for (int j = 0; j < 2; j++) {
            int idx = base + 16 * j + g;
            es[j] = (idx < e1) ? __ldg(&g_es[idx]) : make_float2(0.0f, 0.0f);
        }
#pragma unroll
        for (int j = 0; j < 2; j++) {
            uint4 v = __ldg(&x4[__float_as_int(es[j].x) * 2 + c0]);
            h8_fma2(acc2, v, pack_w2(es[j].y));
        }
    }

    // reduce over the 16 edge-slot groups (same c0: xor bits 1..4)
#pragma unroll
    for (int off = 2; off <= 16; off <<= 1) {
#pragma unroll
        for (int i = 0; i < 4; i++) {
            unsigned long long t = __shfl_xor_sync(0xffffffffu, acc2[i], off);
            ADD_F32X2(acc2[i], acc2[i], t);
        }
    }

    float accf[8];
#pragma unroll
    for (int i = 0; i < 4; i++) {
        unsigned int lo, hi;
        asm("mov.b64 {%0, %1}, %2;" : "=r"(lo), "=r"(hi) : "l"(acc2[i]));
        accf[2 * i]     = __uint_as_float(lo);
        accf[2 * i + 1] = __uint_as_float(hi);
    }

    // in-warp linear: agg channel k (0..15) lives in accf[k&7] of lane (k>>3)
    float o = bs[lane];
#pragma unroll
    for (int k = 0; k < FEAT_IN; k++) {
        float ak = __shfl_sync(0xffffffffu, accf[k & 7], k >> 3);
        o = fmaf(ak, Ws[k * HID + lane], o);
    }
    out[n * HID + lane] = __float2half(elu(o));
}

// -------- FC1 with packed f32x2 FMA: g_fc1 += H @ Wfc1; resets g_cnt --------
__global__ __launch_bounds__(256)
void fc1_kernel(const float* __restrict__ H, const float* __restrict__ Wfc1) {
    // reset bucket counters for the next graph replay (512 blocks * 256 >= N)
    int gid = blockIdx.x * 256 + threadIdx.x;
    if (gid < N_NODES) g_cnt[gid] = 0;

    __shared__ float Hs[TILE_K * N_GRAPHS];   // [k][m] layout, 16 KB
    int tid = threadIdx.x;
    int k0 = blockIdx.x * TILE_K;

    for (int i = tid; i < TILE_K * N_GRAPHS; i += 256) {
        int m = i / TILE_K;
        int k = i - m * TILE_K;
        Hs[k * N_GRAPHS + m] = H[m * K_FC + k0 + k];   // coalesced global read
    }
    __syncthreads();

    unsigned long long acc2[8];
#pragma unroll
    for (int i = 0; i < 8; i++) acc2[i] = 0ULL;

    for (int k = 0; k < TILE_K; k++) {
        float wv = __ldg(&Wfc1[(k0 + k) * FC_HID + tid]);     // coalesced
        unsigned long long wv2 = pack_w2(wv);
        const ulonglong2* hp = (const ulonglong2*)&Hs[k * N_GRAPHS];
        ulonglong2 p0 = hp[0], p1 = hp[1], p2 = hp[2], p3 = hp[3];
        FMA_F32X2(acc2[0], p0.x, wv2, acc2[0]);
        FMA_F32X2(acc2[1], p0.y, wv2, acc2[1]);
        FMA_F32X2(acc2[2], p1.x, wv2, acc2[2]);
        FMA_F32X2(acc2[3], p1.y, wv2, acc2[3]);
        FMA_F32X2(acc2[4], p2.x, wv2, acc2[4]);
        FMA_F32X2(acc2[5], p2.y, wv2, acc2[5]);
        FMA_F32X2(acc2[6], p3.x, wv2, acc2[6]);
        FMA_F32X2(acc2[7], p3.y, wv2, acc2[7]);
    }
#pragma unroll
    for (int i = 0; i < 8; i++) {
        unsigned int lo, hi;
        asm("mov.b64 {%0, %1}, %2;" : "=r"(lo), "=r"(hi) : "l"(acc2[i]));
        atomicAdd(&g_fc1[(2 * i)     * FC_HID + tid], __uint_as_float(lo));
        atomicAdd(&g_fc1[(2 * i + 1) * FC_HID + tid], __uint_as_float(hi));
    }
}

// -------- FC2: out[16,64] = elu(g_fc1 + bfc1) @ Wfc2 + bfc2 --------
__global__ __launch_bounds__(1024)
void fc2_kernel(const float* __restrict__ bfc1,
                const float* __restrict__ Wfc2,
                const float* __restrict__ bfc2,
                float* __restrict__ out) {
    __shared__ float s[N_GRAPHS * FC_HID];   // 16 KB
    int tid = threadIdx.x;
    for (int i = tid; i < N_GRAPHS * FC_HID; i += 1024) {
        float v = g_fc1[i] + bfc1[i & (FC_HID - 1)];
        s[i] = elu(v);
    }
    __syncthreads();

    int m = tid >> 6;
    int j = tid & 63;
    float acc = bfc2[j];
#pragma unroll 8
    for (int k = 0; k < FC_HID; k++)
        acc = fmaf(s[m * FC_HID + k], __ldg(&Wfc2[k * LATENT + j]), acc);
    out[m * LATENT + j] = acc;
}

extern "C" void kernel_launch(void* const* d_in, const int* in_sizes, int n_in,
                              void* d_out, int out_size) {
    // ---- size-based input mapping (ordering-agnostic) ----
    const float *x = 0, *ea = 0, *W1 = 0, *Wfc1 = 0, *bfc1 = 0, *Wfc2 = 0, *bfc2 = 0;
    const float *Wh[2] = {0, 0};       // W2, W3 (both 1024 elems, relative order kept)
    const float *bh[3] = {0, 0, 0};    // b1, b2, b3 (all 32 elems, relative order kept)
    const void  *ei = 0;
    int nWh = 0, nbh = 0;
    for (int i = 0; i < n_in; i++) {
        switch (in_sizes[i]) {
            case 1048576:  x    = (const float*)d_in[i]; break;  // 65536*16
            case 2097152:  ea   = (const float*)d_in[i]; break;  // E
            case 512:      W1   = (const float*)d_in[i]; break;  // 16*32
            case 1024:     if (nWh < 2) Wh[nWh++] = (const float*)d_in[i]; break;
            case 32:       if (nbh < 3) bh[nbh++] = (const float*)d_in[i]; break;
            case 33554432: Wfc1 = (const float*)d_in[i]; break;  // 131072*256
            case 256:      bfc1 = (const float*)d_in[i]; break;
            case 16384:    Wfc2 = (const float*)d_in[i]; break;  // 256*64
            case 64:       bfc2 = (const float*)d_in[i]; break;
            case 4194304:  ei   = d_in[i]; break;                // 2*E
            default: break;
        }
    }
    const float *W2 = Wh[0], *W3 = Wh[1];
    const float *b1 = bh[0], *b2 = bh[1], *b3 = bh[2];
    float* out = (float*)d_out;

    void *xhp, *hAhp, *hBhp, *hAp;
    cudaGetSymbolAddress(&xhp, g_xh);
    cudaGetSymbolAddress(&hAhp, g_hAh);
    cudaGetSymbolAddress(&hBhp, g_hBh);
    cudaGetSymbolAddress(&hAp, g_hA);

    // ---- single-pass bucket CSR + x->fp16; g_cnt reset by fc1 ----
    fill_kernel<<<E_EDGES / 256, 256>>>((const unsigned int*)ei, ea, x);   // 1

    // ---- layer 1: xh[N,16] -> hAh[N,32] (fp16) ----
    agg_linear16h_kernel<<<N_NODES / 8, 256>>>((const __half*)xhp, W1, b1,
                                               (__half*)hAhp);             // 2
    // ---- layer 2: hAh -> hBh (fp16) ----
    agg_linear32h_kernel<true><<<N_NODES / 8, 256>>>((const __half*)hAhp, W2, b2,
                                                     (__half*)hBhp, 0);    // 3
    // ---- layer 3: hBh -> hA (fp32, for FC1) ----  (4th launch — profiled)
    agg_linear32h_kernel<false><<<N_NODES / 8, 256>>>((const __half*)hBhp, W3, b3,
                                                      0, (float*)hAp);     // 4

    // ---- FC1 (g_fc1 pre-zeroed by fill; resets g_cnt) ----
    fc1_kernel<<<K_FC / TILE_K, 256>>>((const float*)hAp, Wfc1);           // 5

    // ---- FC2 -> output ----
    fc2_kernel<<<1, 1024>>>(bfc1, Wfc2, bfc2, out);                        // 6
}

// round 14
// speedup vs baseline: 1.1502x; 1.0142x over previous
#include <cuda_runtime.h>
#include <cuda_fp16.h>
#include <math.h>

#define N_NODES   65536
#define E_EDGES   2097152
#define FEAT_IN   16
#define HID       32
#define N_GRAPHS  16
#define K_FC      131072      // 4096 * 32
#define FC_HID    256
#define LATENT    64
#define TILE_K    256
#define SLOTS     96          // bucket capacity per node; P(Poisson(32) > 96) ~ 1e-18

// Packed fp32x2 FMA (sm_103a FFMA2) — only reachable via PTX fma.rn.f32x2.
#define FMA_F32X2(d, a, b, c) \
    asm("fma.rn.f32x2 %0, %1, %2, %3;" : "=l"(d) : "l"(a), "l"(b), "l"(c))

// -------- scratch (static device globals; no runtime allocation) --------
__device__ float2 g_es[N_NODES * SLOTS];   // bucketed (src_bits, w); 48MB
__device__ int    g_cnt[N_NODES];          // zero-init; reset by fc1 each call
__device__ __half g_xh[N_NODES * FEAT_IN]; // fp16 copy of x (2MB)
__device__ __half g_hAh[N_NODES * HID];    // fp16 layer-1 output (4MB)
__device__ __half g_hBh[N_NODES * HID];    // fp16 layer-2 output (4MB)
__device__ float  g_hA[N_NODES * HID];     // fp32 layer-3 output (for FC1)
__device__ float  g_fc1[N_GRAPHS * FC_HID]; // zeroed by fill_kernel each call

__device__ __forceinline__ float elu(float v) {
    return v > 0.0f ? v : expm1f(v);
}

// Per-block dtype self-detection: if buffer is int64, hi-words of the first 32
// entries are all zero (indices < 65536); for int32 data they're random indices.
__device__ __forceinline__ int block_detect_is64(const unsigned int* ei32, int* s_is64) {
    if (threadIdx.x < 32) {
        unsigned int hi = ei32[threadIdx.x * 2 + 1];
        unsigned int ball = __ballot_sync(0xffffffffu, hi != 0u);
        if (threadIdx.x == 0) *s_is64 = (ball == 0u) ? 1 : 0;
    }
    __syncthreads();
    return *s_is64;
}

// -------- single-pass bucket fill (1 edge/thread) + x->fp16 + g_fc1 reset --------
__global__ __launch_bounds__(256)
void fill_kernel(const unsigned int* __restrict__ ei32, const float* __restrict__ w,
                 const float* __restrict__ x) {
    __shared__ int s_is64;
    int is64 = block_detect_is64(ei32, &s_is64);
    if (blockIdx.x == 0) {
        for (int i = threadIdx.x; i < N_GRAPHS * FC_HID; i += 256) g_fc1[i] = 0.0f;
    }
    long long e = (long long)blockIdx.x * 256 + threadIdx.x;
    // x -> half: first 4096 blocks convert exactly N*16 elements
    if (e < (long long)N_NODES * FEAT_IN) g_xh[e] = __float2half(x[e]);

    int s = is64 ? (int)ei32[2 * e]             : (int)ei32[e];
    int d = is64 ? (int)ei32[2 * (E_EDGES + e)] : (int)ei32[E_EDGES + e];
    float wv = w[e];
    int p = atomicAdd(&g_cnt[d], 1);
    if (p < SLOTS) g_es[d * SLOTS + p] = make_float2(__int_as_float(s), wv);
}

// Convert a uint4 of 8 fp16 values and FMA into 8 fp32 accumulators.
__device__ __forceinline__ void h8_fma(float* acc, uint4 v, float w) {
    float2 f0 = __half22float2(*reinterpret_cast<__half2*>(&v.x));
    float2 f1 = __half22float2(*reinterpret_cast<__half2*>(&v.y));
    float2 f2 = __half22float2(*reinterpret_cast<__half2*>(&v.z));
    float2 f3 = __half22float2(*reinterpret_cast<__half2*>(&v.w));
    acc[0] = fmaf(f0.x, w, acc[0]);
    acc[1] = fmaf(f0.y, w, acc[1]);
    acc[2] = fmaf(f1.x, w, acc[2]);
    acc[3] = fmaf(f1.y, w, acc[3]);
    acc[4] = fmaf(f2.x, w, acc[4]);
    acc[5] = fmaf(f2.y, w, acc[5]);
    acc[6] = fmaf(f3.x, w, acc[6]);
    acc[7] = fmaf(f3.y, w, acc[7]);
}

// -------- fused agg + linear + ELU, CIN=32 fp16 gather (R10 form) --------
// c0 = lane&3 owns channels 8c0..8c0+7 (uint4 = 16B of a 64B fp16 row);
// g = lane>>2 owns one of 8 edge slots; 32-edge batches (4 sub-batches in flight).
template <bool OUT_HALF>
__global__ __launch_bounds__(256)
void agg_linear32h_kernel(const __half* __restrict__ h,
                          const float* __restrict__ W,
                          const float* __restrict__ b,
                          __half* __restrict__ outh,
                          float* __restrict__ outf) {
    __shared__ float Ws[HID * HID];
    __shared__ float bs[HID];
    int tid = threadIdx.x;
    for (int i = tid; i < HID * HID; i += 256) Ws[i] = W[i];
    if (tid < HID) bs[tid] = b[tid];
    __syncthreads();

    int n = blockIdx.x * 8 + (tid >> 5);
    int lane = tid & 31;
    int c0 = lane & 3;
    int g = lane >> 2;
    int cnt = g_cnt[n];
    if (cnt > SLOTS) cnt = SLOTS;
    int e0 = n * SLOTS;
    int e1 = e0 + cnt;

    float acc[8] = {0.f, 0.f, 0.f, 0.f, 0.f, 0.f, 0.f, 0.f};
    const uint4* h4 = (const uint4*)h;    // row n = h4[n*4 .. n*4+3]

    for (int base = e0; base < e1; base += 32) {
        float2 es[4];
#pragma unroll
        for (int j = 0; j < 4; j++) {
            int idx = base + 8 * j + g;
            es[j] = (idx < e1) ? __ldg(&g_es[idx]) : make_float2(0.0f, 0.0f);
        }
#pragma unroll
        for (int j = 0; j < 4; j++) {
            uint4 v = __ldg(&h4[__float_as_int(es[j].x) * 4 + c0]);
            h8_fma(acc, v, es[j].y);
        }
    }

    // reduce over the 8 edge-slot groups (same c0: xor bits 2..4)
#pragma unroll
    for (int off = 4; off <= 16; off <<= 1) {
#pragma unroll
        for (int i = 0; i < 8; i++)
            acc[i] += __shfl_xor_sync(0xffffffffu, acc[i], off);
    }

    // in-warp linear: agg channel k lives in acc[k&7] of lane (k>>3)
    float o = bs[lane];
#pragma unroll
    for (int k = 0; k < HID; k++) {
        float ak = __shfl_sync(0xffffffffu, acc[k & 7], k >> 3);
        o = fmaf(ak, Ws[k * HID + lane], o);
    }
    float r = elu(o);
    if (OUT_HALF) outh[n * HID + lane] = __float2half(r);
    else          outf[n * HID + lane] = r;
}

// -------- fused agg + linear + ELU, CIN=16 fp16 gather (R10 form) --------
__global__ __launch_bounds__(256)
void agg_linear16h_kernel(const __half* __restrict__ xh,
                          const float* __restrict__ W,
                          const float* __restrict__ b,
                          __half* __restrict__ out) {
    __shared__ float Ws[FEAT_IN * HID];
    __shared__ float bs[HID];
    int tid = threadIdx.x;
    for (int i = tid; i < FEAT_IN * HID; i += 256) Ws[i] = W[i];
    if (tid < HID) bs[tid] = b[tid];
    __syncthreads();

    int n = blockIdx.x * 8 + (tid >> 5);
    int lane = tid & 31;
    int c0 = lane & 1;
    int g = lane >> 1;
    int cnt = g_cnt[n];
    if (cnt > SLOTS) cnt = SLOTS;
    int e0 = n * SLOTS;
    int e1 = e0 + cnt;

    float acc[8] = {0.f, 0.f, 0.f, 0.f, 0.f, 0.f, 0.f, 0.f};
    const uint4* x4 = (const uint4*)xh;   // row n = x4[n*2 .. n*2+1]

    for (int base = e0; base < e1; base += 32) {
        float2 es[2];
#pragma unroll
        for (int j = 0; j < 2; j++) {
            int idx = base + 16 * j + g;
            es[j] = (idx < e1) ? __ldg(&g_es[idx]) : make_float2(0.0f, 0.0f);
        }
#pragma unroll
        for (int j = 0; j < 2; j++) {
            uint4 v = __ldg(&x4[__float_as_int(es[j].x) * 2 + c0]);
            h8_fma(acc, v, es[j].y);
        }
    }

    // reduce over the 16 edge-slot groups (same c0: xor bits 1..4)
#pragma unroll
    for (int off = 2; off <= 16; off <<= 1) {
#pragma unroll
        for (int i = 0; i < 8; i++)
            acc[i] += __shfl_xor_sync(0xffffffffu, acc[i], off);
    }

    // in-warp linear: agg channel k (0..15) lives in acc[k&7] of lane (k>>3)
    float o = bs[lane];
#pragma unroll
    for (int k = 0; k < FEAT_IN; k++) {
        float ak = __shfl_sync(0xffffffffu, acc[k & 7], k >> 3);
        o = fmaf(ak, Ws[k * HID + lane], o);
    }
    out[n * HID + lane] = __float2half(elu(o));
}

// -------- FC1 with packed f32x2 FMA: g_fc1 += H @ Wfc1; resets g_cnt --------
__global__ __launch_bounds__(256)
void fc1_kernel(const float* __restrict__ H, const float* __restrict__ Wfc1) {
    // reset bucket counters for the next graph replay (512 blocks * 256 >= N)
    int gid = blockIdx.x * 256 + threadIdx.x;
    if (gid < N_NODES) g_cnt[gid] = 0;

    __shared__ float Hs[TILE_K * N_GRAPHS];   // [k][m] layout, 16 KB
    int tid = threadIdx.x;
    int k0 = blockIdx.x * TILE_K;

    for (int i = tid; i < TILE_K * N_GRAPHS; i += 256) {
        int m = i / TILE_K;
        int k = i - m * TILE_K;
        Hs[k * N_GRAPHS + m] = H[m * K_FC + k0 + k];   // coalesced global read
    }
    __syncthreads();

    unsigned long long acc2[8];
#pragma unroll
    for (int i = 0; i < 8; i++) acc2[i] = 0ULL;

    for (int k = 0; k < TILE_K; k++) {
        float wv = __ldg(&Wfc1[(k0 + k) * FC_HID + tid]);     // coalesced
        unsigned long long wv2;
        unsigned int wu = __float_as_uint(wv);
        asm("mov.b64 %0, {%1, %2};" : "=l"(wv2) : "r"(wu), "r"(wu));
        const ulonglong2* hp = (const ulonglong2*)&Hs[k * N_GRAPHS];
        ulonglong2 p0 = hp[0], p1 = hp[1], p2 = hp[2], p3 = hp[3];
        FMA_F32X2(acc2[0], p0.x, wv2, acc2[0]);
        FMA_F32X2(acc2[1], p0.y, wv2, acc2[1]);
        FMA_F32X2(acc2[2], p1.x, wv2, acc2[2]);
        FMA_F32X2(acc2[3], p1.y, wv2, acc2[3]);
        FMA_F32X2(acc2[4], p2.x, wv2, acc2[4]);
        FMA_F32X2(acc2[5], p2.y, wv2, acc2[5]);
        FMA_F32X2(acc2[6], p3.x, wv2, acc2[6]);
        FMA_F32X2(acc2[7], p3.y, wv2, acc2[7]);
    }
#pragma unroll
    for (int i = 0; i < 8; i++) {
        unsigned int lo, hi;
        asm("mov.b64 {%0, %1}, %2;" : "=r"(lo), "=r"(hi) : "l"(acc2[i]));
        atomicAdd(&g_fc1[(2 * i)     * FC_HID + tid], __uint_as_float(lo));
        atomicAdd(&g_fc1[(2 * i + 1) * FC_HID + tid], __uint_as_float(hi));
    }
}

// -------- FC2: out[16,64] = elu(g_fc1 + bfc1) @ Wfc2 + bfc2 --------
__global__ __launch_bounds__(1024)
void fc2_kernel(const float* __restrict__ bfc1,
                const float* __restrict__ Wfc2,
                const float* __restrict__ bfc2,
                float* __restrict__ out) {
    __shared__ float s[N_GRAPHS * FC_HID];   // 16 KB
    int tid = threadIdx.x;
    for (int i = tid; i < N_GRAPHS * FC_HID; i += 1024) {
        float v = g_fc1[i] + bfc1[i & (FC_HID - 1)];
        s[i] = elu(v);
    }
    __syncthreads();

    int m = tid >> 6;
    int j = tid & 63;
    float acc = bfc2[j];
#pragma unroll 8
    for (int k = 0; k < FC_HID; k++)
        acc = fmaf(s[m * FC_HID + k], __ldg(&Wfc2[k * LATENT + j]), acc);
    out[m * LATENT + j] = acc;
}

extern "C" void kernel_launch(void* const* d_in, const int* in_sizes, int n_in,
                              void* d_out, int out_size) {
    // ---- size-based input mapping (ordering-agnostic) ----
    const float *x = 0, *ea = 0, *W1 = 0, *Wfc1 = 0, *bfc1 = 0, *Wfc2 = 0, *bfc2 = 0;
    const float *Wh[2] = {0, 0};       // W2, W3 (both 1024 elems, relative order kept)
    const float *bh[3] = {0, 0, 0};    // b1, b2, b3 (all 32 elems, relative order kept)
    const void  *ei = 0;
    int nWh = 0, nbh = 0;
    for (int i = 0; i < n_in; i++) {
        switch (in_sizes[i]) {
            case 1048576:  x    = (const float*)d_in[i]; break;  // 65536*16
            case 2097152:  ea   = (const float*)d_in[i]; break;  // E
            case 512:      W1   = (const float*)d_in[i]; break;  // 16*32
            case 1024:     if (nWh < 2) Wh[nWh++] = (const float*)d_in[i]; break;
            case 32:       if (nbh < 3) bh[nbh++] = (const float*)d_in[i]; break;
            case 33554432: Wfc1 = (const float*)d_in[i]; break;  // 131072*256
            case 256:      bfc1 = (const float*)d_in[i]; break;
            case 16384:    Wfc2 = (const float*)d_in[i]; break;  // 256*64
            case 64:       bfc2 = (const float*)d_in[i]; break;
            case 4194304:  ei   = d_in[i]; break;                // 2*E
            default: break;
        }
    }
    const float *W2 = Wh[0], *W3 = Wh[1];
    const float *b1 = bh[0], *b2 = bh[1], *b3 = bh[2];
    float* out = (float*)d_out;

    void *xhp, *hAhp, *hBhp, *hAp;
    cudaGetSymbolAddress(&xhp, g_xh);
    cudaGetSymbolAddress(&hAhp, g_hAh);
    cudaGetSymbolAddress(&hBhp, g_hBh);
    cudaGetSymbolAddress(&hAp, g_hA);

    // ---- single-pass bucket CSR + x->fp16; g_cnt reset by fc1 ----
    fill_kernel<<<E_EDGES / 256, 256>>>((const unsigned int*)ei, ea, x);   // 1

    // ---- layer 1: xh[N,16] -> hAh[N,32] (fp16) ----
    agg_linear16h_kernel<<<N_NODES / 8, 256>>>((const __half*)xhp, W1, b1,
                                               (__half*)hAhp);             // 2
    // ---- layer 2: hAh -> hBh (fp16) ----
    agg_linear32h_kernel<true><<<N_NODES / 8, 256>>>((const __half*)hAhp, W2, b2,
                                                     (__half*)hBhp, 0);    // 3
    // ---- layer 3: hBh -> hA (fp32, for FC1) ----  (4th launch — profiled)
    agg_linear32h_kernel<false><<<N_NODES / 8, 256>>>((const __half*)hBhp, W3, b3,
                                                      0, (float*)hAp);     // 4

    // ---- FC1 (g_fc1 pre-zeroed by fill; resets g_cnt) ----
    fc1_kernel<<<K_FC / TILE_K, 256>>>((const float*)hAp, Wfc1);           // 5

    // ---- FC2 -> output ----
    fc2_kernel<<<1, 1024>>>(bfc1, Wfc2, bfc2, out);                        // 6
}